// round 10
// baseline (speedup 1.0000x reference)
#include <cuda_runtime.h>
#include <cuda_bf16.h>

#define B_ 8
#define T_ 256
#define U_ 65
#define D_ 512
#define BTU_ (B_ * T_ * U_)
#define RSTRIDE 136              // floats per (b,t) row: 4 planes + pad
#define PAD 64                   // zero pad rows in front (module zero-init)
#define RTOT 392                 // PAD + T + back pad (covers prefetch to diag dE+PF)
#define PF_DEPTH 2               // prefetch distance (ring of 2)

#define GRID 888                 // 6 CTAs/SM x 148 SMs -> all co-resident
#define DPB  B_                  // blocks 0..7 = dp consumers
#define LSE_CTAS (GRID - DPB)    // 880 producer CTAs
#define LSE_WARPS (LSE_CTAS * 8)

#define BIAS 10.0f
#define INV_LN2 1.4426950408889634f
#define LN2 0.6931471805599453f

// Plane-split row layout (RSTRIDE floats per (b,t) row):
//   [  0.. 33] labelOdd : slot i = label(t, 2i-1), i=1..32; slots 0,33 stay 0
//   [ 34.. 66] blankEven: slot i = blank(t, 2i),   i=0..32
//   [ 67.. 99] blankOdd : slot i = blank(t, 2i+1), i=0..31; slot 32 stays 0
//   [100..132] labelEven: slot i = label(t, 2i),   i=0..32
//   [133..135] pad = 0
// Pad rows/slots are never written; module zero-init keeps them 0 forever.
__device__ float g_probs[B_ * RTOT * RSTRIDE];   // ~1.7 MB (lives in L2)
__device__ int   g_cnt[B_ * T_];                 // reset by dp CTAs each run

__device__ __forceinline__ float ex2f(float x) {
    float y; asm("ex2.approx.ftz.f32 %0, %1;" : "=f"(y) : "f"(x)); return y;
}
__device__ __forceinline__ float lg2f(float x) {
    float y; asm("lg2.approx.ftz.f32 %0, %1;" : "=f"(y) : "f"(x)); return y;
}

// Watermark probe: check 32 contiguous row counters at once (acquire + ballot).
__device__ __forceinline__ int probe32(const int* cnt, int cw, int lane) {
    int r = cw + 1 + lane;
    r = r > (T_ - 1) ? (T_ - 1) : r;
    int c;
    asm volatile("ld.acquire.gpu.global.u32 %0, [%1];" : "=r"(c) : "l"(cnt + r));
    const unsigned done = __ballot_sync(0xffffffffu, c >= U_);
    const unsigned nd = ~done;
    const int adv = nd ? (__ffs(nd) - 1) : 32;
    const int ncw = cw + adv;
    return ncw > (T_ - 1) ? (T_ - 1) : ncw;
}

#define GATE(RN)                                            \
    while (cw < (RN)) {                                     \
        const int ncw = probe32(cnt, cw, lane);             \
        if (ncw == cw) __nanosleep(60);                     \
        cw = ncw;                                           \
    }

__global__ void __launch_bounds__(256, 6)
fused_kernel(const float* __restrict__ logits, const int* __restrict__ targets,
             const int* __restrict__ srcLen, const int* __restrict__ tgtLen,
             float* __restrict__ out) {
    const int tid = threadIdx.x;
    const int wid = tid >> 5;
    const int lane = tid & 31;

    // ========================= LSE producer CTAs =========================
    if (blockIdx.x >= DPB) {
        for (int r = (blockIdx.x - DPB) * 8 + wid; r < BTU_; r += LSE_WARPS) {
            // t-major enumeration: small-t rows complete first, all batches.
            const int t = r / (B_ * U_);
            const int bu = r - t * (B_ * U_);
            const int b = bu / U_;
            const int u = bu - b * U_;
            const size_t row = ((size_t)(b * T_ + t)) * U_ + u;

            const float4* row4 = reinterpret_cast<const float4*>(logits + row * D_);
            const float4 v0 = row4[lane];
            const float4 v1 = row4[lane + 32];
            const float4 v2 = row4[lane + 64];
            const float4 v3 = row4[lane + 96];

            float m = v0.x;
            m = fmaxf(m, v0.y); m = fmaxf(m, v0.z); m = fmaxf(m, v0.w);
            m = fmaxf(m, v1.x); m = fmaxf(m, v1.y); m = fmaxf(m, v1.z); m = fmaxf(m, v1.w);
            m = fmaxf(m, v2.x); m = fmaxf(m, v2.y); m = fmaxf(m, v2.z); m = fmaxf(m, v2.w);
            m = fmaxf(m, v3.x); m = fmaxf(m, v3.y); m = fmaxf(m, v3.z); m = fmaxf(m, v3.w);
#pragma unroll
            for (int o = 16; o; o >>= 1) m = fmaxf(m, __shfl_xor_sync(0xffffffffu, m, o));

            float s = 0.f;
            s += __expf(v0.x - m) + __expf(v0.y - m) + __expf(v0.z - m) + __expf(v0.w - m);
            s += __expf(v1.x - m) + __expf(v1.y - m) + __expf(v1.z - m) + __expf(v1.w - m);
            s += __expf(v2.x - m) + __expf(v2.y - m) + __expf(v2.z - m) + __expf(v2.w - m);
            s += __expf(v3.x - m) + __expf(v3.y - m) + __expf(v3.z - m) + __expf(v3.w - m);
#pragma unroll
            for (int o = 16; o; o >>= 1) s += __shfl_xor_sync(0xffffffffu, s, o);

            const float lse = m + __logf(s);
            const float blankLogit = __shfl_sync(0xffffffffu, v3.w, 31);   // elem 511

            if (lane == 0) {
                const int lbl = (u < U_ - 1) ? targets[b * (U_ - 1) + u] : 0;
                const float labelLogit = __ldg(logits + row * D_ + lbl);
                const float pb = ex2f((blankLogit - lse) * INV_LN2 + BIAS);
                const float pl = ex2f((labelLogit - lse) * INV_LN2 + BIAS);
                const int base = (b * RTOT + PAD + t) * RSTRIDE;
                if (u & 1) {
                    g_probs[base + 0  + ((u + 1) >> 1)] = pl;   // labelOdd
                    g_probs[base + 67 + ((u - 1) >> 1)] = pb;   // blankOdd
                } else {
                    g_probs[base + 34  + (u >> 1)] = pb;        // blankEven
                    g_probs[base + 100 + (u >> 1)] = pl;        // labelEven
                }
                asm volatile("red.release.gpu.global.add.u32 [%0], 1;"
                             :: "l"(g_cnt + b * T_ + t) : "memory");
            }
        }
        return;
    }

    // ========================= DP consumer CTAs =========================
    if (tid >= 32) return;   // one warp per batch
    const int b = blockIdx.x;
    const int* cnt = g_cnt + b * T_;
    const float* gP = g_probs + (size_t)b * RTOT * RSTRIDE;

    const int tE = srcLen[b] - 1;
    const int uE = tgtLen[b];
    const int dE = tE + uE;

    const int u0 = 2 * lane;

    float aE = (lane == 0) ? 1.0f : 0.0f;   // u = u0
    float aO = 0.0f;                        // u = u0+1
    float aX = 0.0f;                        // u = 64 (lane 31)
    float expShift = 0.0f;

    // d=0 base offsets (diag d lives at base + d*RSTRIDE). Same mapping as R9.
    const int oB0 = (PAD - 1 - u0) * RSTRIDE + 34 + lane;    // blank(t0-1, u0)
    const int oL0 = (PAD - u0) * RSTRIDE + lane;             // label(t0, u0-1); lane0 -> 0-slot
    const int oB1 = (PAD - 2 - u0) * RSTRIDE + 67 + lane;    // blank(t0-2, u0+1)
    const int oL1 = (PAD - 1 - u0) * RSTRIDE + 100 + lane;   // label(t0-1, u0)
    const int oBx = (PAD - 65) * RSTRIDE + 66;               // blank(d-65, 64)
    const int oLx = (PAD - 64) * RSTRIDE + 32;               // label(d-64, 63)

    int cw = -1;   // contiguous watermark: rows <= cw confirmed produced

    float rB0[2], rL0[2], rB1[2], rL1[2], rBx[2], rLx[2];

    // Prologue: gate rows <= PF_DEPTH, prefetch diagonals 1..2.
    GATE(PF_DEPTH < (T_ - 1) ? PF_DEPTH : (T_ - 1));
#pragma unroll
    for (int q = 1; q <= PF_DEPTH; ++q) {
        const int off = q * RSTRIDE;
        const int s = q & 1;
        rB0[s] = __ldcg(gP + oB0 + off);
        rL0[s] = __ldcg(gP + oL0 + off);
        rB1[s] = __ldcg(gP + oB1 + off);
        rL1[s] = __ldcg(gP + oL1 + off);
        rBx[s] = __ldcg(gP + oBx + off);
        rLx[s] = __ldcg(gP + oLx + off);
    }

#pragma unroll 2
    for (int d = 1; d <= dE; ++d) {
        const int s = d & 1;

        const float nbr = __shfl_up_sync(0xffffffffu, aO, 1);   // lane0: x0-slot kills it
        const float rE = fmaf(aE, rB0[s], nbr * rL0[s]);
        const float rO = fmaf(aO, rB1[s], aE * rL1[s]);
        const float rX = fmaf(aX, rBx[s], aO * rLx[s]);
        aE = rE; aO = rO; aX = rX;

        if ((d & 31) == 0) {   // warp-uniform power-of-2 renormalization
            float mval = fmaxf(aE, fmaxf(aO, aX));
#pragma unroll
            for (int o = 16; o; o >>= 1) mval = fmaxf(mval, __shfl_xor_sync(0xffffffffu, mval, o));
            const int e = ilogbf(mval);
            const float sc = __uint_as_float((unsigned)(127 - e) << 23);   // 2^-e
            aE *= sc; aO *= sc; aX *= sc;
            expShift += (float)e;
        }

        // Gate + prefetch diagonal d+PF_DEPTH into the slot just consumed.
        const int q = d + PF_DEPTH;
        const int rowNeed = q < T_ ? q : (T_ - 1);
        GATE(rowNeed);
        const int off = q * RSTRIDE;
        rB0[s] = __ldcg(gP + oB0 + off);
        rL0[s] = __ldcg(gP + oL0 + off);
        rB1[s] = __ldcg(gP + oB1 + off);
        rL1[s] = __ldcg(gP + oL1 + off);
        rBx[s] = __ldcg(gP + oBx + off);
        rLx[s] = __ldcg(gP + oLx + off);
    }

    GATE(tE);   // final blank term's row (also covers dE==0)

    const bool ownE = (uE == u0);
    const bool ownO = (uE == u0 + 1);
    const bool ownX = (uE == 64) && (lane == 31);
    if (ownE || ownO || ownX) {
        float alphaF = ownX ? aX : (ownO ? aO : aE);
        if (dE == 0) alphaF = 1.0f;
        const int rb = (PAD + tE) * RSTRIDE;
        const float fb = (uE & 1) ? __ldcg(gP + rb + 67 + ((uE - 1) >> 1))
                                  : __ldcg(gP + rb + 34 + (uE >> 1));
        const float alpha_log2 = lg2f(alphaF) + expShift - BIAS * (float)dE;
        const float fb_log2 = lg2f(fb) - BIAS;
        out[b] = -LN2 * (alpha_log2 + fb_log2);
    }

    __syncwarp();
    // Watermark hit T-1 => every producer bump for batch b has happened.
    // Reset counters for the next graph replay.
    for (int i = lane; i < T_; i += 32) g_cnt[b * T_ + i] = 0;
}

// ---------------------------------------------------------------------------
extern "C" void kernel_launch(void* const* d_in, const int* in_sizes, int n_in,
                              void* d_out, int out_size) {
    const float* logits = (const float*)d_in[0];
    const int* targets = (const int*)d_in[1];
    const int* srcLen = (const int*)d_in[2];
    const int* tgtLen = (const int*)d_in[3];
    float* out = (float*)d_out;

    fused_kernel<<<GRID, 256>>>(logits, targets, srcLen, tgtLen, out);
}

// round 11
// speedup vs baseline: 2.0576x; 2.0576x over previous
#include <cuda_runtime.h>
#include <cuda_bf16.h>

#define B_ 8
#define T_ 256
#define U_ 65
#define D_ 512
#define BTU_ (B_ * T_ * U_)
#define RSTRIDE 136              // floats per (b,t) row: 4 planes + pad
#define PAD 64                   // zero pad rows in front
#define RTOT 392                 // PAD + T + 72 back-pad rows

#define BIAS 10.0f
#define INV_LN2 1.4426950408889634f
#define LN2 0.6931471805599453f

// Plane-split row layout (RSTRIDE floats):
//   [  0.. 33] labelOdd : slot i = label(t, 2i-1), i=1..32; slots 0,33 stay 0
//   [ 34.. 66] blankEven: slot i = blank(t, 2i),   i=0..32
//   [ 67.. 99] blankOdd : slot i = blank(t, 2i+1), i=0..31; slot 32 stays 0
//   [100..132] labelEven: slot i = label(t, 2i),   i=0..32
//   [133..135] pad = 0
__device__ float g_probs[B_ * T_ * RSTRIDE];

__device__ __forceinline__ float ex2f(float x) {
    float y; asm("ex2.approx.ftz.f32 %0, %1;" : "=f"(y) : "f"(x)); return y;
}
__device__ __forceinline__ float lg2f(float x) {
    float y; asm("lg2.approx.ftz.f32 %0, %1;" : "=f"(y) : "f"(x)); return y;
}

// ---------------------------------------------------------------------------
// Kernel 1: per-row logsumexp over D=512 -> biased linear probs, plane-split.
// One warp per row; HBM-bound. (Identical to round 9 — proven 42us.)
// ---------------------------------------------------------------------------
__global__ void __launch_bounds__(256) lse_kernel(const float* __restrict__ logits,
                                                  const int* __restrict__ targets) {
    const int gw = (blockIdx.x * 256 + threadIdx.x) >> 5;
    const int lane = threadIdx.x & 31;
    if (gw >= BTU_) return;

    const float4* row4 = reinterpret_cast<const float4*>(logits + (size_t)gw * D_);
    const float4 v0 = row4[lane];
    const float4 v1 = row4[lane + 32];
    const float4 v2 = row4[lane + 64];
    const float4 v3 = row4[lane + 96];

    float m = v0.x;
    m = fmaxf(m, v0.y); m = fmaxf(m, v0.z); m = fmaxf(m, v0.w);
    m = fmaxf(m, v1.x); m = fmaxf(m, v1.y); m = fmaxf(m, v1.z); m = fmaxf(m, v1.w);
    m = fmaxf(m, v2.x); m = fmaxf(m, v2.y); m = fmaxf(m, v2.z); m = fmaxf(m, v2.w);
    m = fmaxf(m, v3.x); m = fmaxf(m, v3.y); m = fmaxf(m, v3.z); m = fmaxf(m, v3.w);
#pragma unroll
    for (int o = 16; o; o >>= 1) m = fmaxf(m, __shfl_xor_sync(0xffffffffu, m, o));

    float s = 0.f;
    s += __expf(v0.x - m) + __expf(v0.y - m) + __expf(v0.z - m) + __expf(v0.w - m);
    s += __expf(v1.x - m) + __expf(v1.y - m) + __expf(v1.z - m) + __expf(v1.w - m);
    s += __expf(v2.x - m) + __expf(v2.y - m) + __expf(v2.z - m) + __expf(v2.w - m);
    s += __expf(v3.x - m) + __expf(v3.y - m) + __expf(v3.z - m) + __expf(v3.w - m);
#pragma unroll
    for (int o = 16; o; o >>= 1) s += __shfl_xor_sync(0xffffffffu, s, o);

    const float lse = m + __logf(s);
    const float blankLogit = __shfl_sync(0xffffffffu, v3.w, 31);   // element 511

    if (lane == 0) {
        const int b = gw / (T_ * U_);
        const int rem = gw % (T_ * U_);
        const int t = rem / U_;
        const int u = rem % U_;
        const int lbl = (u < U_ - 1) ? targets[b * (U_ - 1) + u] : 0;
        const float labelLogit = __ldg(logits + (size_t)gw * D_ + lbl);
        const float pb = ex2f((blankLogit - lse) * INV_LN2 + BIAS);
        const float pl = ex2f((labelLogit - lse) * INV_LN2 + BIAS);
        const int base = (b * T_ + t) * RSTRIDE;
        if (u & 1) {
            g_probs[base + 0  + ((u + 1) >> 1)] = pl;   // labelOdd
            g_probs[base + 67 + ((u - 1) >> 1)] = pb;   // blankOdd
        } else {
            g_probs[base + 34  + (u >> 1)] = pb;        // blankEven
            g_probs[base + 100 + (u >> 1)] = pl;        // labelEven
        }
    }
}

// ---------------------------------------------------------------------------
// Kernel 2: linear-domain alpha DP, one CTA/batch. Two diagonals composed per
// macro-step (coefficient products off the critical chain); renorm hoisted
// out of the hot loop (between 16-macro chunks). Maskless: zero padding is
// the mask. Lane l owns u={2l,2l+1}; lane 31 also u=64.
// ---------------------------------------------------------------------------
extern __shared__ float s_dyn[];

__global__ void __launch_bounds__(128) dp_kernel(const int* __restrict__ srcLen,
                                                 const int* __restrict__ tgtLen,
                                                 float* __restrict__ out) {
    const int b = blockIdx.x;
    const int tid = threadIdx.x;

    float* sP = s_dyn;   // [RTOT * RSTRIDE]

    {   // Zero pad rows front/back; copy valid rows (float4 contiguous).
        const float4 zr = make_float4(0.f, 0.f, 0.f, 0.f);
        float4* s4 = reinterpret_cast<float4*>(sP);
        const int rowQ = RSTRIDE / 4;                    // 34
        const int frontQ = PAD * rowQ;
        const int backStart = (PAD + T_) * rowQ;
        const int backQ = (RTOT - PAD - T_) * rowQ;
        for (int i = tid; i < frontQ; i += 128) s4[i] = zr;
        for (int i = tid; i < backQ; i += 128) s4[backStart + i] = zr;
        const float4* g4 = reinterpret_cast<const float4*>(g_probs + (size_t)b * T_ * RSTRIDE);
#pragma unroll 4
        for (int i = tid; i < T_ * rowQ; i += 128) s4[frontQ + i] = g4[i];
    }
    __syncthreads();
    if (tid >= 32) return;

    const int lane = tid;
    const int tE = srcLen[b] - 1;
    const int uE = tgtLen[b];
    const int dE = tE + uE;

    const int u0 = 2 * lane;

    float aE = (lane == 0) ? 1.0f : 0.0f;   // u = u0
    float aO = 0.0f;                        // u = u0+1
    float aX = 0.0f;                        // u = 64 (lane 31)
    float expShift = 0.0f;

    // Per-lane constant slot offsets; address(d) = sP + d*RSTRIDE + offset.
    const int oB0 = (PAD - 1 - u0) * RSTRIDE + 34 + lane;    // blank(t0-1, u0)
    const int oL0 = (PAD - u0) * RSTRIDE + lane;             // label(t0, u0-1); lane0 -> 0
    const int oB1 = (PAD - 2 - u0) * RSTRIDE + 67 + lane;    // blank(t0-2, u0+1)
    const int oL1 = (PAD - 1 - u0) * RSTRIDE + 100 + lane;   // label(t0-1, u0)
    const int oBx = (PAD - 65) * RSTRIDE + 66;               // blank(d-65, 64)
    const int oLx = (PAD - 64) * RSTRIDE + 32;               // label(d-64, 63)
    // Shifted coefficients (value of B1/L1 at lane-1), needed by composition:
    const int oB1s = (PAD - u0) * RSTRIDE + 67 + lane - 1;       // lane0: finite junk x0
    const int oL1s = (PAD + 1 - u0) * RSTRIDE + 100 + lane - 1;  // lane0: killed by L0p=0

    // Single diagonal step at diag d (pointer pd = sP + d*RSTRIDE).
#define SINGLE(pd)                                                   \
    {                                                                \
        const float B0 = (pd)[oB0], L0 = (pd)[oL0];                  \
        const float B1 = (pd)[oB1], L1 = (pd)[oL1];                  \
        const float Bx = (pd)[oBx], Lx = (pd)[oLx];                  \
        const float shO = __shfl_up_sync(0xffffffffu, aO, 1);        \
        const float nE = fmaf(aE, B0, shO * L0);                     \
        const float nO = fmaf(aO, B1, aE * L1);                      \
        const float nX = fmaf(aX, Bx, aO * Lx);                      \
        aE = nE; aO = nO; aX = nX;                                   \
    }

    // Composed 2-diagonal macro step at diags (d, d+1), pd = sP + d*RSTRIDE.
#define MACRO(pd)                                                    \
    {                                                                \
        const float B0 = (pd)[oB0], L0 = (pd)[oL0];                  \
        const float B1 = (pd)[oB1], L1 = (pd)[oL1];                  \
        const float Bx = (pd)[oBx];                                  \
        const float B1s = (pd)[oB1s], L1s = (pd)[oL1s];              \
        const float B0p = (pd)[oB0 + RSTRIDE], L0p = (pd)[oL0 + RSTRIDE]; \
        const float B1p = (pd)[oB1 + RSTRIDE], L1p = (pd)[oL1 + RSTRIDE]; \
        const float Bxp = (pd)[oBx + RSTRIDE], Lxp = (pd)[oLx + RSTRIDE]; \
        const float c1  = B0 * B0p;                                  \
        const float c2  = fmaf(L0, B0p, B1s * L0p);                  \
        const float c3  = L1s * L0p;                                 \
        const float cO1 = B1 * B1p;                                  \
        const float cO2 = fmaf(L1, B1p, B0 * L1p);                   \
        const float cO3 = L0 * L1p;                                  \
        const float cX1 = Bx * Bxp;                                  \
        const float cX2 = B1 * Lxp;                                  \
        const float cX3 = L1 * Lxp;                                  \
        const float shO = __shfl_up_sync(0xffffffffu, aO, 1);        \
        const float shE = __shfl_up_sync(0xffffffffu, aE, 1);        \
        const float nE = fmaf(aE, c1, fmaf(shO, c2, shE * c3));      \
        const float nO = fmaf(aO, cO1, fmaf(aE, cO2, shO * cO3));    \
        const float nX = fmaf(aX, cX1, fmaf(aO, cX2, aE * cX3));     \
        aE = nE; aO = nO; aX = nX;                                   \
    }

#define RENORM                                                                    \
    {                                                                             \
        float mval = fmaxf(aE, fmaxf(aO, aX));                                    \
        for (int o = 16; o; o >>= 1)                                              \
            mval = fmaxf(mval, __shfl_xor_sync(0xffffffffu, mval, o));            \
        const int e = ilogbf(mval);                                               \
        const float sc = __uint_as_float((unsigned)(127 - e) << 23);              \
        aE *= sc; aO *= sc; aX *= sc;                                             \
        expShift += (float)e;                                                     \
    }

    int d = 1;
    const float* pd = sP + RSTRIDE;          // sP + d*RSTRIDE at d=1
    if (dE & 1) {                            // make remaining diag count even
        SINGLE(pd);
        d = 2; pd += RSTRIDE;
    }

    // Chunks of 16 macros (32 diagonals) with renorm between — branch-free body.
    while (d + 31 <= dE) {
#pragma unroll 4
        for (int k = 0; k < 16; ++k) {
            MACRO(pd);
            pd += 2 * RSTRIDE;
        }
        d += 32;
        RENORM;
    }
    // Tail macros (< 16): within renorm safety margin.
    while (d + 1 <= dE) {
        MACRO(pd);
        pd += 2 * RSTRIDE;
        d += 2;
    }

    const bool ownE = (uE == u0);
    const bool ownO = (uE == u0 + 1);
    const bool ownX = (uE == 64) && (lane == 31);
    if (ownE || ownO || ownX) {
        float alphaF = ownX ? aX : (ownO ? aO : aE);
        if (dE == 0) alphaF = 1.0f;
        const int rb = (PAD + tE) * RSTRIDE;
        const float fb = (uE & 1) ? sP[rb + 67 + ((uE - 1) >> 1)]
                                  : sP[rb + 34 + (uE >> 1)];
        const float alpha_log2 = lg2f(alphaF) + expShift - BIAS * (float)dE;
        const float fb_log2 = lg2f(fb) - BIAS;
        out[b] = -LN2 * (alpha_log2 + fb_log2);
    }
#undef SINGLE
#undef MACRO
#undef RENORM
}

// ---------------------------------------------------------------------------
extern "C" void kernel_launch(void* const* d_in, const int* in_sizes, int n_in,
                              void* d_out, int out_size) {
    const float* logits = (const float*)d_in[0];
    const int* targets = (const int*)d_in[1];
    const int* srcLen = (const int*)d_in[2];
    const int* tgtLen = (const int*)d_in[3];
    float* out = (float*)d_out;

    lse_kernel<<<BTU_ / 8, 256>>>(logits, targets);

    const int smemBytes = RTOT * RSTRIDE * (int)sizeof(float);  // 213248 B
    cudaFuncSetAttribute(dp_kernel, cudaFuncAttributeMaxDynamicSharedMemorySize, smemBytes);
    dp_kernel<<<B_, 128, smemBytes>>>(srcLen, tgtLen, out);
}